// round 11
// baseline (speedup 1.0000x reference)
#include <cuda_runtime.h>
#include <cuda_fp16.h>
#include <stdint.h>

// ---------------- problem dims ----------------
#define BATCH   4
#define T_SEQ   2048
#define D_MODEL 1024
#define D_FF    4096
#define M_TOTAL (BATCH * T_SEQ)   // 8192

// ---------------- device scratch ----------------
__device__ __half g_E[M_TOTAL * D_MODEL];     // ema(spikes) fp16 (16 MB)
__device__ __half g_W1h[D_FF * D_MODEL];      // W1 fp16          (8 MB)
__device__ int g_count;
#define SPIKE_CAP (1 << 20)
__device__ int g_list[SPIKE_CAP];

#define FLAG_T 0.35f      // screen margin; exact recheck decides vs 0.5

// ---------------- helpers ----------------
__device__ __forceinline__ uint32_t smem_u32(const void* p) {
    return (uint32_t)__cvta_generic_to_shared(p);
}
__device__ __forceinline__ void cp_async16(uint32_t saddr, const void* gaddr) {
    asm volatile("cp.async.cg.shared.global [%0], [%1], 16;\n" :: "r"(saddr), "l"(gaddr));
}
__device__ __forceinline__ void cp_commit() {
    asm volatile("cp.async.commit_group;\n" ::);
}
template <int N>
__device__ __forceinline__ void cp_wait() {
    asm volatile("cp.async.wait_group %0;\n" :: "n"(N));
}
__device__ __forceinline__ void ldmatrix_x4(uint32_t* r, uint32_t addr) {
    asm volatile("ldmatrix.sync.aligned.m8n8.x4.shared.b16 {%0,%1,%2,%3}, [%4];\n"
                 : "=r"(r[0]), "=r"(r[1]), "=r"(r[2]), "=r"(r[3]) : "r"(addr));
}
// fp16 MMA with fp16 accumulate (rate-neutral vs f32-acc; halves acc registers)
__device__ __forceinline__ void mma_f16acc(uint32_t* c, const uint32_t* a, const uint32_t* b) {
    asm volatile(
        "mma.sync.aligned.m16n8k16.row.col.f16.f16.f16.f16 "
        "{%0,%1}, {%2,%3,%4,%5}, {%6,%7}, {%0,%1};\n"
        : "+r"(c[0]), "+r"(c[1])
        : "r"(a[0]), "r"(a[1]), "r"(a[2]), "r"(a[3]), "r"(b[0]), "r"(b[1]));
}

// ---------------- fused prep + EMA ----------------
// blocks [0,256):    EMA chains (chunk 128, halo 128; 0.9^128 ~ 1.4e-6), fp16 out
// blocks [256,1440): reset counter + zero output + W1 fp32->fp16
__global__ void __launch_bounds__(256) prep_ema_kernel(const float* __restrict__ spikes,
                                                       const float4* __restrict__ w1_in,
                                                       float4* __restrict__ out) {
    if (blockIdx.x < 256) {
        int idx = blockIdx.x * 256 + threadIdx.x;     // 0 .. 65535
        int d = idx & (D_MODEL - 1);
        int q = idx >> 10;                            // 0..63
        int b = q >> 4;                               // 0..3
        int c = q & 15;                               // chunk of 128
        const float* sp = spikes + (size_t)b * T_SEQ * D_MODEL + d;
        __half* eb = g_E + (size_t)b * T_SEQ * D_MODEL + d;
        int t0 = c * 128;
        float acc = 0.f;
        if (c) {
            for (int t = t0 - 128; t < t0; t += 8) {
                float v[8];
#pragma unroll
                for (int i = 0; i < 8; i++) v[i] = sp[(size_t)(t + i) * D_MODEL];
#pragma unroll
                for (int i = 0; i < 8; i++) acc = fmaf(0.9f, acc, 0.1f * v[i]);
            }
        }
        for (int t = t0; t < t0 + 128; t += 8) {
            float v[8];
#pragma unroll
            for (int i = 0; i < 8; i++) v[i] = sp[(size_t)(t + i) * D_MODEL];
#pragma unroll
            for (int i = 0; i < 8; i++) {
                acc = fmaf(0.9f, acc, 0.1f * v[i]);
                eb[(size_t)(t + i) * D_MODEL] = __float2half_rn(acc);
            }
        }
    } else {
        int bid = blockIdx.x - 256;                   // 0..1183
        if (bid == 0 && threadIdx.x == 0) g_count = 0;
        int tid = bid * 256 + threadIdx.x;
        int stride = 1184 * 256;
        int nz = (M_TOTAL * D_MODEL) / 4;
        float4 z = make_float4(0.f, 0.f, 0.f, 0.f);
        for (int i = tid; i < nz; i += stride) out[i] = z;
        int n4 = (D_FF * D_MODEL) / 4;
        uint2* w1o = reinterpret_cast<uint2*>(g_W1h);
        for (int i = tid; i < n4; i += stride) {
            float4 v = w1_in[i];
            __half2 h01 = __floats2half2_rn(v.x, v.y);
            __half2 h23 = __floats2half2_rn(v.z, v.w);
            uint2 p;
            p.x = *reinterpret_cast<uint32_t*>(&h01);
            p.y = *reinterpret_cast<uint32_t*>(&h23);
            w1o[i] = p;
        }
    }
}

// ---------------- fp16 GEMM screen: BK=32 stages, 3 CTAs/SM target ----------------
// CTA 128x128, 256 thr, 8 warps (2M x 4N), warp tile 64x32, 3-stage cp.async.
#define BK      32
#define ROW_B   80                           // 64B row + 16B pad: conflict-free ldmatrix
#define TILE_B  (128 * ROW_B)                // 10240 per operand tile
#define STAGE_BYTES (2 * TILE_B)             // 20480
#define NSTAGE  3
#define GEMM_SMEM (NSTAGE * STAGE_BYTES)     // 61440 -> 3 CTAs/SM (184 KB)

__global__ void __launch_bounds__(256, 3) gemm_screen_kernel() {
    extern __shared__ __align__(128) char smem[];
    uint32_t sb = smem_u32(smem);

    const int tid  = threadIdx.x;
    const int lane = tid & 31;
    const int w    = tid >> 5;
    const int wm   = w & 1;
    const int wn   = w >> 1;
    const int m0   = blockIdx.y * 128;
    const int n0   = blockIdx.x * 128;

    uint32_t acc[4][4][2];                    // fp16x2 accumulators (32 regs)
#pragma unroll
    for (int i = 0; i < 4; i++)
#pragma unroll
        for (int j = 0; j < 4; j++) {
            acc[i][j][0] = 0u; acc[i][j][1] = 0u;
        }

    const int lrow = tid >> 1;          // 0..127 (one row per 2 threads)
    const int lck  = tid & 1;           // 2 chunks of 16B per 64B row... (x2 below)

    auto fill = [&](int buf, int kt) {
        uint32_t base = sb + buf * STAGE_BYTES;
        const int k0 = kt * BK;
        const __half* ga = g_E   + (size_t)(m0 + lrow) * D_MODEL + k0 + lck * 16;
        const __half* gb = g_W1h + (size_t)(n0 + lrow) * D_MODEL + k0 + lck * 16;
        uint32_t sa  = base + lrow * ROW_B + lck * 32;
        uint32_t sbb = base + TILE_B + lrow * ROW_B + lck * 32;
        // each thread: 2 chunks for A, 2 for B (16B apart)
        cp_async16(sa, ga);
        cp_async16(sa + 16, ga + 8);
        cp_async16(sbb, gb);
        cp_async16(sbb + 16, gb + 8);
    };

    auto compute = [&](int buf) {
        uint32_t abase = sb + buf * STAGE_BYTES
                       + (wm * 64 + (lane & 15)) * ROW_B + (lane >> 4) * 16;
        uint32_t bbase = sb + buf * STAGE_BYTES + TILE_B
                       + (wn * 32 + (lane & 7) + ((lane >> 4) << 3)) * ROW_B
                       + ((lane >> 3) & 1) * 16;
#pragma unroll
        for (int kk = 0; kk < 2; kk++) {         // 2 x (k=16)
            uint32_t a[4][4], b[4][2];
#pragma unroll
            for (int i = 0; i < 4; i++)
                ldmatrix_x4(a[i], abase + i * 16 * ROW_B + kk * 32);
#pragma unroll
            for (int j = 0; j < 2; j++) {
                uint32_t r[4];
                ldmatrix_x4(r, bbase + j * 16 * ROW_B + kk * 32);
                b[2 * j][0] = r[0]; b[2 * j][1] = r[1];
                b[2 * j + 1][0] = r[2]; b[2 * j + 1][1] = r[3];
            }
#pragma unroll
            for (int i = 0; i < 4; i++)
#pragma unroll
                for (int jn = 0; jn < 4; jn++)
                    mma_f16acc(acc[i][jn], a[i], b[jn]);
        }
    };

    fill(0, 0); cp_commit();
    fill(1, 1); cp_commit();

    const int KT = D_MODEL / BK;   // 32
    for (int kt = 0; kt < KT; kt++) {
        cp_wait<1>();
        __syncthreads();
        if (kt + 2 < KT) fill((kt + 2) % NSTAGE, kt + 2);
        cp_commit();               // empty tail groups keep wait<1> exact
        compute(kt % NSTAGE);
    }

    // epilogue: flag screen candidates only
#pragma unroll
    for (int i = 0; i < 4; i++) {
#pragma unroll
        for (int jn = 0; jn < 4; jn++) {
            int row = m0 + wm * 64 + i * 16 + (lane >> 2);
            int col = n0 + wn * 32 + jn * 8 + (lane & 3) * 2;
#pragma unroll
            for (int h = 0; h < 2; h++) {            // h=0: row, h=1: row+8
                __half2 hv = *reinterpret_cast<__half2*>(&acc[i][jn][h]);
                float2 fv = __half22float2(hv);
                if (fv.x > FLAG_T) {
                    int pos = atomicAdd(&g_count, 1);
                    if (pos < SPIKE_CAP) g_list[pos] = (row + h * 8) * D_FF + col;
                }
                if (fv.y > FLAG_T) {
                    int pos = atomicAdd(&g_count, 1);
                    if (pos < SPIKE_CAP) g_list[pos] = (row + h * 8) * D_FF + col + 1;
                }
            }
        }
    }
}

// ---------------- recheck (fp16 E x fp32 W1) + exact fixup; expected ~0 fires ----------------
__global__ void recheck_fixup_kernel(const float* __restrict__ spikes,
                                     const float* __restrict__ W1,
                                     const float* __restrict__ Wr,
                                     const float* __restrict__ W2,
                                     float* __restrict__ out) {
    __shared__ float red[256];
    __shared__ float bcast;
    int c = g_count;
    if (c > SPIKE_CAP) c = SPIKE_CAP;
    for (int i = blockIdx.x; i < c; i += gridDim.x) {
        int g  = g_list[i];
        int f  = g & (D_FF - 1);
        int bt = g >> 12;
        const __half* ef = g_E + (size_t)bt * D_MODEL;
        const float* w1 = W1 + (size_t)f * D_MODEL;
        float s = 0.f;
        for (int d = threadIdx.x; d < D_MODEL; d += blockDim.x)
            s += __half2float(ef[d]) * w1[d];
        red[threadIdx.x] = s;
        __syncthreads();
        for (int o = 128; o > 0; o >>= 1) {
            if (threadIdx.x < o) red[threadIdx.x] += red[threadIdx.x + o];
            __syncthreads();
        }
        if (threadIdx.x == 0) bcast = red[0];
        __syncthreads();
        if (bcast > 0.5f) {
            const float* sp = spikes + (size_t)bt * D_MODEL;
            const float* wr = Wr + (size_t)f * D_MODEL;
            float s2 = 0.f;
            for (int d = threadIdx.x; d < D_MODEL; d += blockDim.x) s2 += sp[d] * wr[d];
            red[threadIdx.x] = s2;
            __syncthreads();
            for (int o = 128; o > 0; o >>= 1) {
                if (threadIdx.x < o) red[threadIdx.x] += red[threadIdx.x + o];
                __syncthreads();
            }
            float rv = 1.f / (1.f + expf(-red[0]));
            float* op = out + (size_t)bt * D_MODEL;
            for (int d = threadIdx.x; d < D_MODEL; d += blockDim.x)
                atomicAdd(&op[d], rv * W2[(size_t)d * D_FF + f]);
        }
        __syncthreads();
    }
}

// ---------------- launch ----------------
extern "C" void kernel_launch(void* const* d_in, const int* in_sizes, int n_in,
                              void* d_out, int out_size) {
    const float* spikes = (const float*)d_in[0];  // [B, T, D]
    const float* W1 = (const float*)d_in[1];      // [F, D]
    const float* W2 = (const float*)d_in[2];      // [D, F]
    const float* Wr = (const float*)d_in[3];      // [F, D]
    float* out = (float*)d_out;

    cudaFuncSetAttribute(gemm_screen_kernel,
                         cudaFuncAttributeMaxDynamicSharedMemorySize, GEMM_SMEM);

    prep_ema_kernel<<<1440, 256>>>(spikes, (const float4*)W1, (float4*)out);

    dim3 grid(D_FF / 128, M_TOTAL / 128);         // (32, 64)
    gemm_screen_kernel<<<grid, 256, GEMM_SMEM>>>();

    recheck_fixup_kernel<<<128, 256>>>(spikes, W1, Wr, W2, out);
}

// round 12
// speedup vs baseline: 1.2034x; 1.2034x over previous
#include <cuda_runtime.h>
#include <cuda_fp16.h>
#include <stdint.h>

// ---------------- problem dims ----------------
#define BATCH   4
#define T_SEQ   2048
#define D_MODEL 1024
#define D_FF    4096
#define M_TOTAL (BATCH * T_SEQ)   // 8192

// ---------------- device scratch ----------------
__device__ __half g_E[M_TOTAL * D_MODEL];     // ema(spikes) fp16 (16 MB)
__device__ __half g_W1h[D_FF * D_MODEL];      // W1 fp16          (8 MB)
__device__ int g_count;
#define SPIKE_CAP (1 << 20)
__device__ int g_list[SPIKE_CAP];

#define FLAG_T 0.35f      // screen margin; exact recheck decides vs 0.5

// ---------------- helpers ----------------
__device__ __forceinline__ uint32_t smem_u32(const void* p) {
    return (uint32_t)__cvta_generic_to_shared(p);
}
__device__ __forceinline__ void cp_async16(uint32_t saddr, const void* gaddr) {
    asm volatile("cp.async.cg.shared.global [%0], [%1], 16;\n" :: "r"(saddr), "l"(gaddr));
}
__device__ __forceinline__ void cp_commit() {
    asm volatile("cp.async.commit_group;\n" ::);
}
template <int N>
__device__ __forceinline__ void cp_wait() {
    asm volatile("cp.async.wait_group %0;\n" :: "n"(N));
}
__device__ __forceinline__ void ldmatrix_x4(uint32_t* r, uint32_t addr) {
    asm volatile("ldmatrix.sync.aligned.m8n8.x4.shared.b16 {%0,%1,%2,%3}, [%4];\n"
                 : "=r"(r[0]), "=r"(r[1]), "=r"(r[2]), "=r"(r[3]) : "r"(addr));
}
// fp16 MMA with fp16 accumulate (rate-neutral vs f32-acc; halves acc registers)
__device__ __forceinline__ void mma_f16acc(uint32_t* c, const uint32_t* a, const uint32_t* b) {
    asm volatile(
        "mma.sync.aligned.m16n8k16.row.col.f16.f16.f16.f16 "
        "{%0,%1}, {%2,%3,%4,%5}, {%6,%7}, {%0,%1};\n"
        : "+r"(c[0]), "+r"(c[1])
        : "r"(a[0]), "r"(a[1]), "r"(a[2]), "r"(a[3]), "r"(b[0]), "r"(b[1]));
}

// ---------------- fused prep + EMA (R11 version, measured 24.5us) ----------------
__global__ void __launch_bounds__(256) prep_ema_kernel(const float* __restrict__ spikes,
                                                       const float4* __restrict__ w1_in,
                                                       float4* __restrict__ out) {
    if (blockIdx.x < 256) {
        int idx = blockIdx.x * 256 + threadIdx.x;     // 0 .. 65535
        int d = idx & (D_MODEL - 1);
        int q = idx >> 10;                            // 0..63
        int b = q >> 4;                               // 0..3
        int c = q & 15;                               // chunk of 128
        const float* sp = spikes + (size_t)b * T_SEQ * D_MODEL + d;
        __half* eb = g_E + (size_t)b * T_SEQ * D_MODEL + d;
        int t0 = c * 128;
        float acc = 0.f;
        if (c) {
            for (int t = t0 - 128; t < t0; t += 8) {
                float v[8];
#pragma unroll
                for (int i = 0; i < 8; i++) v[i] = sp[(size_t)(t + i) * D_MODEL];
#pragma unroll
                for (int i = 0; i < 8; i++) acc = fmaf(0.9f, acc, 0.1f * v[i]);
            }
        }
        for (int t = t0; t < t0 + 128; t += 8) {
            float v[8];
#pragma unroll
            for (int i = 0; i < 8; i++) v[i] = sp[(size_t)(t + i) * D_MODEL];
#pragma unroll
            for (int i = 0; i < 8; i++) {
                acc = fmaf(0.9f, acc, 0.1f * v[i]);
                eb[(size_t)(t + i) * D_MODEL] = __float2half_rn(acc);
            }
        }
    } else {
        int bid = blockIdx.x - 256;                   // 0..1183
        if (bid == 0 && threadIdx.x == 0) g_count = 0;
        int tid = bid * 256 + threadIdx.x;
        int stride = 1184 * 256;
        int nz = (M_TOTAL * D_MODEL) / 4;
        float4 z = make_float4(0.f, 0.f, 0.f, 0.f);
        for (int i = tid; i < nz; i += stride) out[i] = z;
        int n4 = (D_FF * D_MODEL) / 4;
        uint2* w1o = reinterpret_cast<uint2*>(g_W1h);
        for (int i = tid; i < n4; i += stride) {
            float4 v = w1_in[i];
            __half2 h01 = __floats2half2_rn(v.x, v.y);
            __half2 h23 = __floats2half2_rn(v.z, v.w);
            uint2 p;
            p.x = *reinterpret_cast<uint32_t*>(&h01);
            p.y = *reinterpret_cast<uint32_t*>(&h23);
            w1o[i] = p;
        }
    }
}

// ---------------- fp16 GEMM screen: BK=64, NSTAGE=2 -> 3 CTAs/SM, 24 warps/SM ----------------
// CTA 128x128, 256 thr, 8 warps (2M x 4N), warp tile 64x32; 16 barrier steps.
#define BK      64
#define ROW_B   144                          // 128B row + 16B pad: conflict-free ldmatrix
#define TILE_B  (128 * ROW_B)                // 18432 per operand tile
#define STAGE_BYTES (2 * TILE_B)             // 36864
#define NSTAGE  2
#define GEMM_SMEM (NSTAGE * STAGE_BYTES)     // 73728 -> 3 CTAs/SM (221 KB)

__global__ void __launch_bounds__(256, 3) gemm_screen_kernel() {
    extern __shared__ __align__(128) char smem[];
    uint32_t sb = smem_u32(smem);

    const int tid  = threadIdx.x;
    const int lane = tid & 31;
    const int w    = tid >> 5;
    const int wm   = w & 1;
    const int wn   = w >> 1;
    const int m0   = blockIdx.y * 128;
    const int n0   = blockIdx.x * 128;

    uint32_t acc[4][4][2];                    // fp16x2 accumulators (32 regs)
#pragma unroll
    for (int i = 0; i < 4; i++)
#pragma unroll
        for (int j = 0; j < 4; j++) {
            acc[i][j][0] = 0u; acc[i][j][1] = 0u;
        }

    const int lrow = tid >> 3;          // 0..31 base row
    const int lck  = tid & 7;           // 16B chunk in row

    auto fill = [&](int buf, int kt) {
        uint32_t base = sb + buf * STAGE_BYTES;
        const int k0 = kt * BK;
        const __half* ga = g_E   + (size_t)(m0 + lrow) * D_MODEL + k0 + lck * 8;
        const __half* gb = g_W1h + (size_t)(n0 + lrow) * D_MODEL + k0 + lck * 8;
        uint32_t sa  = base + lrow * ROW_B + lck * 16;
        uint32_t sbb = base + TILE_B + lrow * ROW_B + lck * 16;
#pragma unroll
        for (int i = 0; i < 4; i++) {   // rows lrow, +32, +64, +96
            cp_async16(sa + i * 32 * ROW_B, ga + (size_t)(i * 32) * D_MODEL);
            cp_async16(sbb + i * 32 * ROW_B, gb + (size_t)(i * 32) * D_MODEL);
        }
    };

    auto compute = [&](int buf) {
        uint32_t abase = sb + buf * STAGE_BYTES
                       + (wm * 64 + (lane & 15)) * ROW_B + (lane >> 4) * 16;
        uint32_t bbase = sb + buf * STAGE_BYTES + TILE_B
                       + (wn * 32 + (lane & 7) + ((lane >> 4) << 3)) * ROW_B
                       + ((lane >> 3) & 1) * 16;
#pragma unroll
        for (int kk = 0; kk < 4; kk++) {         // 4 x (k=16)
            uint32_t a[4][4], b[4][2];
#pragma unroll
            for (int i = 0; i < 4; i++)
                ldmatrix_x4(a[i], abase + i * 16 * ROW_B + kk * 32);
#pragma unroll
            for (int j = 0; j < 2; j++) {
                uint32_t r[4];
                ldmatrix_x4(r, bbase + j * 16 * ROW_B + kk * 32);
                b[2 * j][0] = r[0]; b[2 * j][1] = r[1];
                b[2 * j + 1][0] = r[2]; b[2 * j + 1][1] = r[3];
            }
#pragma unroll
            for (int i = 0; i < 4; i++)
#pragma unroll
                for (int jn = 0; jn < 4; jn++)
                    mma_f16acc(acc[i][jn], a[i], b[jn]);
        }
    };

    fill(0, 0); cp_commit();

    const int KT = D_MODEL / BK;   // 16
    for (int kt = 0; kt < KT; kt++) {
        cp_wait<0>();              // stage kt complete (only group possibly pending: kt+1 not yet issued)
        __syncthreads();           // also closes WAR: all warps finished compute(kt-1) on the buffer we refill
        if (kt + 1 < KT) fill((kt + 1) & 1, kt + 1);
        cp_commit();
        compute(kt & 1);           // overlaps with fill(kt+1) in flight
    }

    // epilogue: flag screen candidates only
#pragma unroll
    for (int i = 0; i < 4; i++) {
#pragma unroll
        for (int jn = 0; jn < 4; jn++) {
            int row = m0 + wm * 64 + i * 16 + (lane >> 2);
            int col = n0 + wn * 32 + jn * 8 + (lane & 3) * 2;
#pragma unroll
            for (int h = 0; h < 2; h++) {            // h=0: row, h=1: row+8
                __half2 hv = *reinterpret_cast<__half2*>(&acc[i][jn][h]);
                float2 fv = __half22float2(hv);
                if (fv.x > FLAG_T) {
                    int pos = atomicAdd(&g_count, 1);
                    if (pos < SPIKE_CAP) g_list[pos] = (row + h * 8) * D_FF + col;
                }
                if (fv.y > FLAG_T) {
                    int pos = atomicAdd(&g_count, 1);
                    if (pos < SPIKE_CAP) g_list[pos] = (row + h * 8) * D_FF + col + 1;
                }
            }
        }
    }
}

// ---------------- recheck (fp16 E x fp32 W1) + exact fixup; expected ~0 fires ----------------
__global__ void recheck_fixup_kernel(const float* __restrict__ spikes,
                                     const float* __restrict__ W1,
                                     const float* __restrict__ Wr,
                                     const float* __restrict__ W2,
                                     float* __restrict__ out) {
    __shared__ float red[256];
    __shared__ float bcast;
    int c = g_count;
    if (c > SPIKE_CAP) c = SPIKE_CAP;
    for (int i = blockIdx.x; i < c; i += gridDim.x) {
        int g  = g_list[i];
        int f  = g & (D_FF - 1);
        int bt = g >> 12;
        const __half* ef = g_E + (size_t)bt * D_MODEL;
        const float* w1 = W1 + (size_t)f * D_MODEL;
        float s = 0.f;
        for (int d = threadIdx.x; d < D_MODEL; d += blockDim.x)
            s += __half2float(ef[d]) * w1[d];
        red[threadIdx.x] = s;
        __syncthreads();
        for (int o = 128; o > 0; o >>= 1) {
            if (threadIdx.x < o) red[threadIdx.x] += red[threadIdx.x + o];
            __syncthreads();
        }
        if (threadIdx.x == 0) bcast = red[0];
        __syncthreads();
        if (bcast > 0.5f) {
            const float* sp = spikes + (size_t)bt * D_MODEL;
            const float* wr = Wr + (size_t)f * D_MODEL;
            float s2 = 0.f;
            for (int d = threadIdx.x; d < D_MODEL; d += blockDim.x) s2 += sp[d] * wr[d];
            red[threadIdx.x] = s2;
            __syncthreads();
            for (int o = 128; o > 0; o >>= 1) {
                if (threadIdx.x < o) red[threadIdx.x] += red[threadIdx.x + o];
                __syncthreads();
            }
            float rv = 1.f / (1.f + expf(-red[0]));
            float* op = out + (size_t)bt * D_MODEL;
            for (int d = threadIdx.x; d < D_MODEL; d += blockDim.x)
                atomicAdd(&op[d], rv * W2[(size_t)d * D_FF + f]);
        }
        __syncthreads();
    }
}

// ---------------- launch ----------------
extern "C" void kernel_launch(void* const* d_in, const int* in_sizes, int n_in,
                              void* d_out, int out_size) {
    const float* spikes = (const float*)d_in[0];  // [B, T, D]
    const float* W1 = (const float*)d_in[1];      // [F, D]
    const float* W2 = (const float*)d_in[2];      // [D, F]
    const float* Wr = (const float*)d_in[3];      // [F, D]
    float* out = (float*)d_out;

    cudaFuncSetAttribute(gemm_screen_kernel,
                         cudaFuncAttributeMaxDynamicSharedMemorySize, GEMM_SMEM);

    prep_ema_kernel<<<1440, 256>>>(spikes, (const float4*)W1, (float4*)out);

    dim3 grid(D_FF / 128, M_TOTAL / 128);         // (32, 64)
    gemm_screen_kernel<<<grid, 256, GEMM_SMEM>>>();

    recheck_fixup_kernel<<<128, 256>>>(spikes, W1, Wr, W2, out);
}

// round 13
// speedup vs baseline: 1.2352x; 1.0264x over previous
#include <cuda_runtime.h>
#include <cuda_fp16.h>
#include <stdint.h>

// ---------------- problem dims ----------------
#define BATCH   4
#define T_SEQ   2048
#define D_MODEL 1024
#define D_FF    4096
#define M_TOTAL (BATCH * T_SEQ)   // 8192

// ---------------- device scratch ----------------
__device__ __half g_E[M_TOTAL * D_MODEL];     // ema(spikes) fp16 (16 MB)
__device__ __half g_W1h[D_FF * D_MODEL];      // W1 fp16          (8 MB)
__device__ int g_count;
#define SPIKE_CAP (1 << 20)
__device__ int g_list[SPIKE_CAP];

#define FLAG_T 0.35f      // screen margin; exact recheck decides vs 0.5

// ---------------- helpers ----------------
__device__ __forceinline__ uint32_t smem_u32(const void* p) {
    return (uint32_t)__cvta_generic_to_shared(p);
}
__device__ __forceinline__ void cp_async16(uint32_t saddr, const void* gaddr) {
    asm volatile("cp.async.cg.shared.global [%0], [%1], 16;\n" :: "r"(saddr), "l"(gaddr));
}
__device__ __forceinline__ void cp_commit() {
    asm volatile("cp.async.commit_group;\n" ::);
}
template <int N>
__device__ __forceinline__ void cp_wait() {
    asm volatile("cp.async.wait_group %0;\n" :: "n"(N));
}
__device__ __forceinline__ void ldmatrix_x4(uint32_t* r, uint32_t addr) {
    asm volatile("ldmatrix.sync.aligned.m8n8.x4.shared.b16 {%0,%1,%2,%3}, [%4];\n"
                 : "=r"(r[0]), "=r"(r[1]), "=r"(r[2]), "=r"(r[3]) : "r"(addr));
}
// fp16 MMA with fp16 accumulate (rate-neutral vs f32-acc; halves acc registers)
__device__ __forceinline__ void mma_f16acc(uint32_t* c, const uint32_t* a, const uint32_t* b) {
    asm volatile(
        "mma.sync.aligned.m16n8k16.row.col.f16.f16.f16.f16 "
        "{%0,%1}, {%2,%3,%4,%5}, {%6,%7}, {%0,%1};\n"
        : "+r"(c[0]), "+r"(c[1])
        : "r"(a[0]), "r"(a[1]), "r"(a[2]), "r"(a[3]), "r"(b[0]), "r"(b[1]));
}

// ---------------- fused prep + EMA ----------------
// blocks [0,256):   EMA chains (chunk 128, halo 64; 0.9^64 ~ 1.2e-3 -> carry err ~5e-4,
//                   same order as fp16 rounding, << 0.15 screen margin)
// blocks [256,768): reset counter + W1 fp32->fp16  (out-zeroing moved into GEMM)
__global__ void __launch_bounds__(256) prep_ema_kernel(const float* __restrict__ spikes,
                                                       const float4* __restrict__ w1_in) {
    if (blockIdx.x < 256) {
        int idx = blockIdx.x * 256 + threadIdx.x;     // 0 .. 65535
        int d = idx & (D_MODEL - 1);
        int q = idx >> 10;                            // 0..63
        int b = q >> 4;                               // 0..3
        int c = q & 15;                               // chunk of 128
        const float* sp = spikes + (size_t)b * T_SEQ * D_MODEL + d;
        __half* eb = g_E + (size_t)b * T_SEQ * D_MODEL + d;
        int t0 = c * 128;
        float acc = 0.f;
        if (c) {
            for (int t = t0 - 64; t < t0; t += 8) {
                float v[8];
#pragma unroll
                for (int i = 0; i < 8; i++) v[i] = sp[(size_t)(t + i) * D_MODEL];
#pragma unroll
                for (int i = 0; i < 8; i++) acc = fmaf(0.9f, acc, 0.1f * v[i]);
            }
        }
        for (int t = t0; t < t0 + 128; t += 8) {
            float v[8];
#pragma unroll
            for (int i = 0; i < 8; i++) v[i] = sp[(size_t)(t + i) * D_MODEL];
#pragma unroll
            for (int i = 0; i < 8; i++) {
                acc = fmaf(0.9f, acc, 0.1f * v[i]);
                eb[(size_t)(t + i) * D_MODEL] = __float2half_rn(acc);
            }
        }
    } else {
        int bid = blockIdx.x - 256;                   // 0..511
        if (bid == 0 && threadIdx.x == 0) g_count = 0;
        int tid = bid * 256 + threadIdx.x;
        int stride = 512 * 256;
        int n4 = (D_FF * D_MODEL) / 4;
        uint2* w1o = reinterpret_cast<uint2*>(g_W1h);
        for (int i = tid; i < n4; i += stride) {
            float4 v = w1_in[i];
            __half2 h01 = __floats2half2_rn(v.x, v.y);
            __half2 h23 = __floats2half2_rn(v.z, v.w);
            uint2 p;
            p.x = *reinterpret_cast<uint32_t*>(&h01);
            p.y = *reinterpret_cast<uint32_t*>(&h23);
            w1o[i] = p;
        }
    }
}

// ---------------- fp16 GEMM screen: BK=64, NSTAGE=2, 3 CTAs/SM (R12 proven) ----------------
// CTA 128x128, 256 thr, 8 warps (2M x 4N), warp tile 64x32; 16 barrier steps.
// Prologue additionally zeroes this CTA's 16KB slice of out (overlapped with mainloop).
#define BK      64
#define ROW_B   144                          // 128B row + 16B pad: conflict-free ldmatrix
#define TILE_B  (128 * ROW_B)                // 18432 per operand tile
#define STAGE_BYTES (2 * TILE_B)             // 36864
#define NSTAGE  2
#define GEMM_SMEM (NSTAGE * STAGE_BYTES)     // 73728 -> 3 CTAs/SM (221 KB)

__global__ void __launch_bounds__(256, 3) gemm_screen_kernel(float4* __restrict__ out) {
    extern __shared__ __align__(128) char smem[];
    uint32_t sb = smem_u32(smem);

    const int tid  = threadIdx.x;
    const int lane = tid & 31;
    const int w    = tid >> 5;
    const int wm   = w & 1;
    const int wn   = w >> 1;
    const int m0   = blockIdx.y * 128;
    const int n0   = blockIdx.x * 128;

    uint32_t acc[4][4][2];                    // fp16x2 accumulators (32 regs)
#pragma unroll
    for (int i = 0; i < 4; i++)
#pragma unroll
        for (int j = 0; j < 4; j++) {
            acc[i][j][0] = 0u; acc[i][j][1] = 0u;
        }

    const int lrow = tid >> 3;          // 0..31 base row
    const int lck  = tid & 7;           // 16B chunk in row

    auto fill = [&](int buf, int kt) {
        uint32_t base = sb + buf * STAGE_BYTES;
        const int k0 = kt * BK;
        const __half* ga = g_E   + (size_t)(m0 + lrow) * D_MODEL + k0 + lck * 8;
        const __half* gb = g_W1h + (size_t)(n0 + lrow) * D_MODEL + k0 + lck * 8;
        uint32_t sa  = base + lrow * ROW_B + lck * 16;
        uint32_t sbb = base + TILE_B + lrow * ROW_B + lck * 16;
#pragma unroll
        for (int i = 0; i < 4; i++) {   // rows lrow, +32, +64, +96
            cp_async16(sa + i * 32 * ROW_B, ga + (size_t)(i * 32) * D_MODEL);
            cp_async16(sbb + i * 32 * ROW_B, gb + (size_t)(i * 32) * D_MODEL);
        }
    };

    auto compute = [&](int buf) {
        uint32_t abase = sb + buf * STAGE_BYTES
                       + (wm * 64 + (lane & 15)) * ROW_B + (lane >> 4) * 16;
        uint32_t bbase = sb + buf * STAGE_BYTES + TILE_B
                       + (wn * 32 + (lane & 7) + ((lane >> 4) << 3)) * ROW_B
                       + ((lane >> 3) & 1) * 16;
#pragma unroll
        for (int kk = 0; kk < 4; kk++) {         // 4 x (k=16)
            uint32_t a[4][4], b[4][2];
#pragma unroll
            for (int i = 0; i < 4; i++)
                ldmatrix_x4(a[i], abase + i * 16 * ROW_B + kk * 32);
#pragma unroll
            for (int j = 0; j < 2; j++) {
                uint32_t r[4];
                ldmatrix_x4(r, bbase + j * 16 * ROW_B + kk * 32);
                b[2 * j][0] = r[0]; b[2 * j][1] = r[1];
                b[2 * j + 1][0] = r[2]; b[2 * j + 1][1] = r[3];
            }
#pragma unroll
            for (int i = 0; i < 4; i++)
#pragma unroll
                for (int jn = 0; jn < 4; jn++)
                    mma_f16acc(acc[i][jn], a[i], b[jn]);
        }
    };

    fill(0, 0); cp_commit();

    // zero this CTA's slice of out (2048 CTAs x 1024 float4 = 8M floats);
    // stores drain in the background under the 16-step mainloop.
    {
        int cta = blockIdx.y * gridDim.x + blockIdx.x;      // 0..2047
        float4* op = out + (size_t)cta * 1024 + tid;
        float4 z = make_float4(0.f, 0.f, 0.f, 0.f);
#pragma unroll
        for (int i = 0; i < 4; i++) op[i * 256] = z;
    }

    const int KT = D_MODEL / BK;   // 16
    for (int kt = 0; kt < KT; kt++) {
        cp_wait<0>();              // stage kt complete (fill(kt+1) not yet issued)
        __syncthreads();           // closes WAR on the recycled buffer
        if (kt + 1 < KT) fill((kt + 1) & 1, kt + 1);
        cp_commit();
        compute(kt & 1);           // overlaps with fill(kt+1) in flight
    }

    // epilogue: flag screen candidates only
#pragma unroll
    for (int i = 0; i < 4; i++) {
#pragma unroll
        for (int jn = 0; jn < 4; jn++) {
            int row = m0 + wm * 64 + i * 16 + (lane >> 2);
            int col = n0 + wn * 32 + jn * 8 + (lane & 3) * 2;
#pragma unroll
            for (int h = 0; h < 2; h++) {            // h=0: row, h=1: row+8
                __half2 hv = *reinterpret_cast<__half2*>(&acc[i][jn][h]);
                float2 fv = __half22float2(hv);
                if (fv.x > FLAG_T) {
                    int pos = atomicAdd(&g_count, 1);
                    if (pos < SPIKE_CAP) g_list[pos] = (row + h * 8) * D_FF + col;
                }
                if (fv.y > FLAG_T) {
                    int pos = atomicAdd(&g_count, 1);
                    if (pos < SPIKE_CAP) g_list[pos] = (row + h * 8) * D_FF + col + 1;
                }
            }
        }
    }
}

// ---------------- recheck (fp16 E x fp32 W1) + exact fixup; expected ~0 fires ----------------
__global__ void recheck_fixup_kernel(const float* __restrict__ spikes,
                                     const float* __restrict__ W1,
                                     const float* __restrict__ Wr,
                                     const float* __restrict__ W2,
                                     float* __restrict__ out) {
    __shared__ float red[256];
    __shared__ float bcast;
    int c = g_count;
    if (c > SPIKE_CAP) c = SPIKE_CAP;
    for (int i = blockIdx.x; i < c; i += gridDim.x) {
        int g  = g_list[i];
        int f  = g & (D_FF - 1);
        int bt = g >> 12;
        const __half* ef = g_E + (size_t)bt * D_MODEL;
        const float* w1 = W1 + (size_t)f * D_MODEL;
        float s = 0.f;
        for (int d = threadIdx.x; d < D_MODEL; d += blockDim.x)
            s += __half2float(ef[d]) * w1[d];
        red[threadIdx.x] = s;
        __syncthreads();
        for (int o = 128; o > 0; o >>= 1) {
            if (threadIdx.x < o) red[threadIdx.x] += red[threadIdx.x + o];
            __syncthreads();
        }
        if (threadIdx.x == 0) bcast = red[0];
        __syncthreads();
        if (bcast > 0.5f) {
            const float* sp = spikes + (size_t)bt * D_MODEL;
            const float* wr = Wr + (size_t)f * D_MODEL;
            float s2 = 0.f;
            for (int d = threadIdx.x; d < D_MODEL; d += blockDim.x) s2 += sp[d] * wr[d];
            red[threadIdx.x] = s2;
            __syncthreads();
            for (int o = 128; o > 0; o >>= 1) {
                if (threadIdx.x < o) red[threadIdx.x] += red[threadIdx.x + o];
                __syncthreads();
            }
            float rv = 1.f / (1.f + expf(-red[0]));
            float* op = out + (size_t)bt * D_MODEL;
            for (int d = threadIdx.x; d < D_MODEL; d += blockDim.x)
                atomicAdd(&op[d], rv * W2[(size_t)d * D_FF + f]);
        }
        __syncthreads();
    }
}

// ---------------- launch ----------------
extern "C" void kernel_launch(void* const* d_in, const int* in_sizes, int n_in,
                              void* d_out, int out_size) {
    const float* spikes = (const float*)d_in[0];  // [B, T, D]
    const float* W1 = (const float*)d_in[1];      // [F, D]
    const float* W2 = (const float*)d_in[2];      // [D, F]
    const float* Wr = (const float*)d_in[3];      // [F, D]
    float* out = (float*)d_out;

    cudaFuncSetAttribute(gemm_screen_kernel,
                         cudaFuncAttributeMaxDynamicSharedMemorySize, GEMM_SMEM);

    prep_ema_kernel<<<768, 256>>>(spikes, (const float4*)W1);

    dim3 grid(D_FF / 128, M_TOTAL / 128);         // (32, 64)
    gemm_screen_kernel<<<grid, 256, GEMM_SMEM>>>((float4*)out);

    recheck_fixup_kernel<<<128, 256>>>(spikes, W1, Wr, W2, out);
}

// round 14
// speedup vs baseline: 1.2681x; 1.0266x over previous
#include <cuda_runtime.h>
#include <cuda_fp16.h>
#include <stdint.h>

// ---------------- problem dims ----------------
#define BATCH   4
#define T_SEQ   2048
#define D_MODEL 1024
#define D_FF    4096
#define M_TOTAL (BATCH * T_SEQ)   // 8192
#define N_TILES 2048              // (8192/128) * (4096/128)
#define GRID_P  444               // 148 SMs x 3 CTAs resident

// ---------------- device scratch ----------------
__device__ __half g_E[M_TOTAL * D_MODEL];     // ema(spikes) fp16 (16 MB)
__device__ __half g_W1h[D_FF * D_MODEL];      // W1 fp16          (8 MB)
__device__ int g_count;
__device__ int g_tile;                        // work-stealing cursor
#define SPIKE_CAP (1 << 20)
__device__ int g_list[SPIKE_CAP];

#define FLAG_T 0.35f      // screen margin; exact recheck decides vs 0.5

// ---------------- helpers ----------------
__device__ __forceinline__ uint32_t smem_u32(const void* p) {
    return (uint32_t)__cvta_generic_to_shared(p);
}
__device__ __forceinline__ void cp_async16(uint32_t saddr, const void* gaddr) {
    asm volatile("cp.async.cg.shared.global [%0], [%1], 16;\n" :: "r"(saddr), "l"(gaddr));
}
__device__ __forceinline__ void cp_commit() {
    asm volatile("cp.async.commit_group;\n" ::);
}
template <int N>
__device__ __forceinline__ void cp_wait() {
    asm volatile("cp.async.wait_group %0;\n" :: "n"(N));
}
__device__ __forceinline__ void ldmatrix_x4(uint32_t* r, uint32_t addr) {
    asm volatile("ldmatrix.sync.aligned.m8n8.x4.shared.b16 {%0,%1,%2,%3}, [%4];\n"
                 : "=r"(r[0]), "=r"(r[1]), "=r"(r[2]), "=r"(r[3]) : "r"(addr));
}
__device__ __forceinline__ void mma_f16acc(uint32_t* c, const uint32_t* a, const uint32_t* b) {
    asm volatile(
        "mma.sync.aligned.m16n8k16.row.col.f16.f16.f16.f16 "
        "{%0,%1}, {%2,%3,%4,%5}, {%6,%7}, {%0,%1};\n"
        : "+r"(c[0]), "+r"(c[1])
        : "r"(a[0]), "r"(a[1]), "r"(a[2]), "r"(a[3]), "r"(b[0]), "r"(b[1]));
}

// ---------------- fused prep + EMA (R13 proven, + g_tile reset) ----------------
__global__ void __launch_bounds__(256) prep_ema_kernel(const float* __restrict__ spikes,
                                                       const float4* __restrict__ w1_in) {
    if (blockIdx.x < 256) {
        int idx = blockIdx.x * 256 + threadIdx.x;     // 0 .. 65535
        int d = idx & (D_MODEL - 1);
        int q = idx >> 10;                            // 0..63
        int b = q >> 4;                               // 0..3
        int c = q & 15;                               // chunk of 128
        const float* sp = spikes + (size_t)b * T_SEQ * D_MODEL + d;
        __half* eb = g_E + (size_t)b * T_SEQ * D_MODEL + d;
        int t0 = c * 128;
        float acc = 0.f;
        if (c) {                                      // halo 64: 0.9^64 ~ 1.2e-3
            for (int t = t0 - 64; t < t0; t += 8) {
                float v[8];
#pragma unroll
                for (int i = 0; i < 8; i++) v[i] = sp[(size_t)(t + i) * D_MODEL];
#pragma unroll
                for (int i = 0; i < 8; i++) acc = fmaf(0.9f, acc, 0.1f * v[i]);
            }
        }
        for (int t = t0; t < t0 + 128; t += 8) {
            float v[8];
#pragma unroll
            for (int i = 0; i < 8; i++) v[i] = sp[(size_t)(t + i) * D_MODEL];
#pragma unroll
            for (int i = 0; i < 8; i++) {
                acc = fmaf(0.9f, acc, 0.1f * v[i]);
                eb[(size_t)(t + i) * D_MODEL] = __float2half_rn(acc);
            }
        }
    } else {
        int bid = blockIdx.x - 256;                   // 0..511
        if (bid == 0 && threadIdx.x == 0) { g_count = 0; g_tile = 0; }
        int tid = bid * 256 + threadIdx.x;
        int stride = 512 * 256;
        int n4 = (D_FF * D_MODEL) / 4;
        uint2* w1o = reinterpret_cast<uint2*>(g_W1h);
        for (int i = tid; i < n4; i += stride) {
            float4 v = w1_in[i];
            __half2 h01 = __floats2half2_rn(v.x, v.y);
            __half2 h23 = __floats2half2_rn(v.z, v.w);
            uint2 p;
            p.x = *reinterpret_cast<uint32_t*>(&h01);
            p.y = *reinterpret_cast<uint32_t*>(&h23);
            w1o[i] = p;
        }
    }
}

// ---------------- persistent work-stealing fp16 GEMM screen ----------------
// 444 resident CTAs pull tiles from g_tile. Per tile: 16 pipeline steps (BK=64,
// NSTAGE=2, R12 cadence). Next tile's stage-0 fill is issued at step 15 (tile
// grabbed at step 13, visible after step-14 barrier) -> no inter-tile bubble.
#define BK      64
#define ROW_B   144
#define TILE_B  (128 * ROW_B)                // 18432
#define STAGE_BYTES (2 * TILE_B)             // 36864
#define GEMM_SMEM (2 * STAGE_BYTES)          // 73728 -> 3 CTAs/SM

__global__ void __launch_bounds__(256, 3) gemm_screen_kernel(float4* __restrict__ out) {
    extern __shared__ __align__(128) char smem[];
    __shared__ int s_cur, s_next;
    uint32_t sb = smem_u32(smem);

    const int tid  = threadIdx.x;
    const int lane = tid & 31;
    const int w    = tid >> 5;
    const int wm   = w & 1;
    const int wn   = w >> 1;

    uint32_t acc[4][4][2];
#pragma unroll
    for (int i = 0; i < 4; i++)
#pragma unroll
        for (int j = 0; j < 4; j++) { acc[i][j][0] = 0u; acc[i][j][1] = 0u; }

    const int lrow = tid >> 3;          // 0..31 base row
    const int lck  = tid & 7;           // 16B chunk in row

    auto fill = [&](int tile, int kt, int buf) {
        uint32_t base = sb + buf * STAGE_BYTES;
        const int m0 = (tile >> 5) * 128;
        const int n0 = (tile & 31) * 128;
        const int k0 = kt * BK;
        const __half* ga = g_E   + (size_t)(m0 + lrow) * D_MODEL + k0 + lck * 8;
        const __half* gb = g_W1h + (size_t)(n0 + lrow) * D_MODEL + k0 + lck * 8;
        uint32_t sa  = base + lrow * ROW_B + lck * 16;
        uint32_t sbb = base + TILE_B + lrow * ROW_B + lck * 16;
#pragma unroll
        for (int i = 0; i < 4; i++) {
            cp_async16(sa + i * 32 * ROW_B, ga + (size_t)(i * 32) * D_MODEL);
            cp_async16(sbb + i * 32 * ROW_B, gb + (size_t)(i * 32) * D_MODEL);
        }
    };

    auto compute = [&](int buf) {
        uint32_t abase = sb + buf * STAGE_BYTES
                       + (wm * 64 + (lane & 15)) * ROW_B + (lane >> 4) * 16;
        uint32_t bbase = sb + buf * STAGE_BYTES + TILE_B
                       + (wn * 32 + (lane & 7) + ((lane >> 4) << 3)) * ROW_B
                       + ((lane >> 3) & 1) * 16;
#pragma unroll
        for (int kk = 0; kk < 4; kk++) {
            uint32_t a[4][4], b[4][2];
#pragma unroll
            for (int i = 0; i < 4; i++)
                ldmatrix_x4(a[i], abase + i * 16 * ROW_B + kk * 32);
#pragma unroll
            for (int j = 0; j < 2; j++) {
                uint32_t r[4];
                ldmatrix_x4(r, bbase + j * 16 * ROW_B + kk * 32);
                b[2 * j][0] = r[0]; b[2 * j][1] = r[1];
                b[2 * j + 1][0] = r[2]; b[2 * j + 1][1] = r[3];
            }
#pragma unroll
            for (int i = 0; i < 4; i++)
#pragma unroll
                for (int jn = 0; jn < 4; jn++)
                    mma_f16acc(acc[i][jn], a[i], b[jn]);
        }
    };

    // initial tile grab
    if (tid == 0) s_cur = atomicAdd(&g_tile, 1);
    __syncthreads();
    int cur = s_cur;
    if (cur >= N_TILES) return;

    fill(cur, 0, 0);
    cp_commit();

    while (cur < N_TILES) {
        int nxt = N_TILES;   // filled in at step 13
        // step 0..15
        for (int kt = 0; kt < 16; kt++) {
            cp_wait<0>();
            __syncthreads();           // closes WAR on recycled buffer + s_next visibility
            if (kt == 0) {
                // zero this tile's out slice (overlapped with remaining 15 steps)
                float4* op = out + (size_t)cur * 1024 + tid;
                float4 z = make_float4(0.f, 0.f, 0.f, 0.f);
#pragma unroll
                for (int i = 0; i < 4; i++) op[i * 256] = z;
            }
            if (kt == 13 && tid == 0) s_next = atomicAdd(&g_tile, 1);
            if (kt < 15) {
                fill(cur, kt + 1, (kt + 1) & 1);
            } else {
                nxt = s_next;          // written step 13, fenced by step-14/15 barriers
                if (nxt < N_TILES) fill(nxt, 0, 0);
            }
            cp_commit();
            compute(kt & 1);
        }

        // epilogue for tile cur: flag screen candidates, reset accumulators
        {
            const int m0 = (cur >> 5) * 128;
            const int n0 = (cur & 31) * 128;
#pragma unroll
            for (int i = 0; i < 4; i++) {
#pragma unroll
                for (int jn = 0; jn < 4; jn++) {
                    int row = m0 + wm * 64 + i * 16 + (lane >> 2);
                    int col = n0 + wn * 32 + jn * 8 + (lane & 3) * 2;
#pragma unroll
                    for (int h = 0; h < 2; h++) {
                        __half2 hv = *reinterpret_cast<__half2*>(&acc[i][jn][h]);
                        float2 fv = __half22float2(hv);
                        if (fv.x > FLAG_T) {
                            int pos = atomicAdd(&g_count, 1);
                            if (pos < SPIKE_CAP) g_list[pos] = (row + h * 8) * D_FF + col;
                        }
                        if (fv.y > FLAG_T) {
                            int pos = atomicAdd(&g_count, 1);
                            if (pos < SPIKE_CAP) g_list[pos] = (row + h * 8) * D_FF + col + 1;
                        }
                        acc[i][jn][h] = 0u;
                    }
                }
            }
        }
        cur = nxt;
    }
}

// ---------------- recheck (fp16 E x fp32 W1) + exact fixup; expected ~0 fires ----------------
__global__ void recheck_fixup_kernel(const float* __restrict__ spikes,
                                     const float* __restrict__ W1,
                                     const float* __restrict__ Wr,
                                     const float* __restrict__ W2,
                                     float* __restrict__ out) {
    __shared__ float red[256];
    __shared__ float bcast;
    int c = g_count;
    if (c > SPIKE_CAP) c = SPIKE_CAP;
    for (int i = blockIdx.x; i < c; i += gridDim.x) {
        int g  = g_list[i];
        int f  = g & (D_FF - 1);
        int bt = g >> 12;
        const __half* ef = g_E + (size_t)bt * D_MODEL;
        const float* w1 = W1 + (size_t)f * D_MODEL;
        float s = 0.f;
        for (int d = threadIdx.x; d < D_MODEL; d += blockDim.x)
            s += __half2float(ef[d]) * w1[d];
        red[threadIdx.x] = s;
        __syncthreads();
        for (int o = 128; o > 0; o >>= 1) {
            if (threadIdx.x < o) red[threadIdx.x] += red[threadIdx.x + o];
            __syncthreads();
        }
        if (threadIdx.x == 0) bcast = red[0];
        __syncthreads();
        if (bcast > 0.5f) {
            const float* sp = spikes + (size_t)bt * D_MODEL;
            const float* wr = Wr + (size_t)f * D_MODEL;
            float s2 = 0.f;
            for (int d = threadIdx.x; d < D_MODEL; d += blockDim.x) s2 += sp[d] * wr[d];
            red[threadIdx.x] = s2;
            __syncthreads();
            for (int o = 128; o > 0; o >>= 1) {
                if (threadIdx.x < o) red[threadIdx.x] += red[threadIdx.x + o];
                __syncthreads();
            }
            float rv = 1.f / (1.f + expf(-red[0]));
            float* op = out + (size_t)bt * D_MODEL;
            for (int d = threadIdx.x; d < D_MODEL; d += blockDim.x)
                atomicAdd(&op[d], rv * W2[(size_t)d * D_FF + f]);
        }
        __syncthreads();
    }
}

// ---------------- launch ----------------
extern "C" void kernel_launch(void* const* d_in, const int* in_sizes, int n_in,
                              void* d_out, int out_size) {
    const float* spikes = (const float*)d_in[0];  // [B, T, D]
    const float* W1 = (const float*)d_in[1];      // [F, D]
    const float* W2 = (const float*)d_in[2];      // [D, F]
    const float* Wr = (const float*)d_in[3];      // [F, D]
    float* out = (float*)d_out;

    cudaFuncSetAttribute(gemm_screen_kernel,
                         cudaFuncAttributeMaxDynamicSharedMemorySize, GEMM_SMEM);

    prep_ema_kernel<<<768, 256>>>(spikes, (const float4*)W1);

    gemm_screen_kernel<<<GRID_P, 256, GEMM_SMEM>>>((float4*)out);

    recheck_fixup_kernel<<<128, 256>>>(spikes, W1, Wr, W2, out);
}